// round 4
// baseline (speedup 1.0000x reference)
#include <cuda_runtime.h>
#include <cstdint>

// ConcatenateMeanMax: out[b] = concat(bond_ft[b], mean(atom_ft[s0], atom_ft[s1]),
//                                     max(atom_ft[s0], atom_ft[s1]))
// DEG = 2 fixed (edge_dst is repeat(arange(n_bonds), 2)).
//
// sm_103 requires 256-bit accesses for L2 evict hints, so each lane handles a
// 32B (8-float) chunk. A half-warp (16 lanes x 32B = 512B) covers one full
// D=128 row; one warp processes two bonds.
//
// L2 policy (kernel is HBM-bound at ~1.03 GB vs a 925 MB compulsory floor; the
// excess is atom-gather L2 misses):
//   atom_ft (102.4 MB table, ~4x reuse, fits L2=126MB) -> ld.global.nc.L2::evict_last (pin)
//   bond_ft (read-once, 205 MB)                        -> ld.global.nc.L2::evict_first
//   out     (write-once, 614 MB)                       -> st.global.cs (streaming)

constexpr int D  = 128;
constexpr int DV = D / 4;  // 32 float4 per row

struct F8 { float4 lo, hi; };

__device__ __forceinline__ F8 ldg_evict_last_v8(const float* p) {
    unsigned a,b,c,d,e,f,g,h;
    asm volatile("ld.global.nc.L2::evict_last.v8.b32 {%0,%1,%2,%3,%4,%5,%6,%7}, [%8];"
                 : "=r"(a),"=r"(b),"=r"(c),"=r"(d),"=r"(e),"=r"(f),"=r"(g),"=r"(h)
                 : "l"(p));
    F8 r;
    r.lo = make_float4(__uint_as_float(a), __uint_as_float(b),
                       __uint_as_float(c), __uint_as_float(d));
    r.hi = make_float4(__uint_as_float(e), __uint_as_float(f),
                       __uint_as_float(g), __uint_as_float(h));
    return r;
}

__device__ __forceinline__ F8 ldg_evict_first_v8(const float* p) {
    unsigned a,b,c,d,e,f,g,h;
    asm volatile("ld.global.nc.L2::evict_first.v8.b32 {%0,%1,%2,%3,%4,%5,%6,%7}, [%8];"
                 : "=r"(a),"=r"(b),"=r"(c),"=r"(d),"=r"(e),"=r"(f),"=r"(g),"=r"(h)
                 : "l"(p));
    F8 r;
    r.lo = make_float4(__uint_as_float(a), __uint_as_float(b),
                       __uint_as_float(c), __uint_as_float(d));
    r.hi = make_float4(__uint_as_float(e), __uint_as_float(f),
                       __uint_as_float(g), __uint_as_float(h));
    return r;
}

__global__ __launch_bounds__(256)
void concat_mean_max_kernel(const float* __restrict__ atom_ft,
                            const float* __restrict__ bond_ft,
                            const int2*  __restrict__ edge_src2,
                            float4* __restrict__ out,
                            int n_bonds)
{
    const int gwarp = (blockIdx.x * blockDim.x + threadIdx.x) >> 5;
    const int lane  = threadIdx.x & 31;

    const int bond = gwarp * 2 + (lane >> 4);   // half-warp -> bond
    if (bond >= n_bonds) return;
    const int j = lane & 15;                    // 32B chunk within row

    const int2 s = __ldg(&edge_src2[bond]);

    // read-once bond row chunk: evict-first
    const F8 bf = ldg_evict_first_v8(bond_ft + (long long)bond * D + j * 8);

    // reused atom row chunks: evict-last (pin table in L2)
    const F8 a0 = ldg_evict_last_v8(atom_ft + (long long)s.x * D + j * 8);
    const F8 a1 = ldg_evict_last_v8(atom_ft + (long long)s.y * D + j * 8);

    F8 mean_v, max_v;
    mean_v.lo.x = (a0.lo.x + a1.lo.x) * 0.5f;  max_v.lo.x = fmaxf(a0.lo.x, a1.lo.x);
    mean_v.lo.y = (a0.lo.y + a1.lo.y) * 0.5f;  max_v.lo.y = fmaxf(a0.lo.y, a1.lo.y);
    mean_v.lo.z = (a0.lo.z + a1.lo.z) * 0.5f;  max_v.lo.z = fmaxf(a0.lo.z, a1.lo.z);
    mean_v.lo.w = (a0.lo.w + a1.lo.w) * 0.5f;  max_v.lo.w = fmaxf(a0.lo.w, a1.lo.w);
    mean_v.hi.x = (a0.hi.x + a1.hi.x) * 0.5f;  max_v.hi.x = fmaxf(a0.hi.x, a1.hi.x);
    mean_v.hi.y = (a0.hi.y + a1.hi.y) * 0.5f;  max_v.hi.y = fmaxf(a0.hi.y, a1.hi.y);
    mean_v.hi.z = (a0.hi.z + a1.hi.z) * 0.5f;  max_v.hi.z = fmaxf(a0.hi.z, a1.hi.z);
    mean_v.hi.w = (a0.hi.w + a1.hi.w) * 0.5f;  max_v.hi.w = fmaxf(a0.hi.w, a1.hi.w);

    // output: streaming stores. lane j owns float4 slots {2j, 2j+1} of each 32-f4 block.
    float4* orow = out + (long long)bond * (3 * DV) + j * 2;
    __stcs(orow,              bf.lo);
    __stcs(orow + 1,          bf.hi);
    __stcs(orow + DV,         mean_v.lo);
    __stcs(orow + DV + 1,     mean_v.hi);
    __stcs(orow + 2 * DV,     max_v.lo);
    __stcs(orow + 2 * DV + 1, max_v.hi);
}

extern "C" void kernel_launch(void* const* d_in, const int* in_sizes, int n_in,
                              void* d_out, int out_size)
{
    const float* atom_ft  = (const float*)d_in[0];   // [N_ATOMS, 128] f32
    const float* bond_ft  = (const float*)d_in[1];   // [N_BONDS, 128] f32
    const int2*  edge_src = (const int2*)d_in[2];    // [N_BONDS*2] i32 -> int2 per bond
    // d_in[3] = edge_dst (structurally repeat(arange, 2)) -- not needed.

    const int n_bonds = in_sizes[1] / D;

    const int threads = 256;                              // 8 warps = 16 bonds/block
    const int bonds_per_block = (threads / 32) * 2;
    const int blocks = (n_bonds + bonds_per_block - 1) / bonds_per_block;

    concat_mean_max_kernel<<<blocks, threads>>>(
        atom_ft, bond_ft, edge_src, (float4*)d_out, n_bonds);
}

// round 5
// speedup vs baseline: 1.0761x; 1.0761x over previous
#include <cuda_runtime.h>
#include <cstdint>

// ConcatenateMeanMax: out[b] = concat(bond_ft[b], mean(atom_ft[s0], atom_ft[s1]),
//                                     max(atom_ft[s0], atom_ft[s1]))
// DEG = 2 fixed (edge_dst is repeat(arange(n_bonds), 2)).
//
// Layout: one warp handles TWO bonds; each lane owns one float4 column slice
// (32 lanes x 16B = 512B = full D=128 row). All 6 row loads (2 bond + 4 atom)
// are issued before compute/stores to maximize outstanding DRAM requests.
//
// Cache policy (what survived testing): __ldcs bond rows + __stcs output keep
// the read-once / write-once streams from evicting the reused atom table.
// (evict_last pinning is a no-op without the persisting-L2 carveout, which the
// harness forbids changing.)

constexpr int D  = 128;
constexpr int DV = D / 4;  // 32 float4 per row

__global__ __launch_bounds__(256)
void concat_mean_max_kernel(const float4* __restrict__ atom_ft,
                            const float4* __restrict__ bond_ft,
                            const int4*  __restrict__ edge_src4,   // 2 bonds' srcs per int4
                            float4* __restrict__ out,
                            int n_bonds)
{
    const int gwarp = (blockIdx.x * blockDim.x + threadIdx.x) >> 5;
    const int lane  = threadIdx.x & 31;

    const int b0 = gwarp * 2;
    const int b1 = b0 + 1;
    if (b0 >= n_bonds) return;
    const bool has_b1 = (b1 < n_bonds);

    // srcs for both bonds in one 16B broadcast load: {s0a,s0b,s1a,s1b}
    const int4 s = __ldg(&edge_src4[gwarp]);

    // ---- issue all loads up front (6 x 512B per warp in flight) ----
    const float4 bf0 = __ldcs(&bond_ft[(long long)b0 * DV + lane]);
    const float4 a00 = __ldg(&atom_ft[(long long)s.x * DV + lane]);
    const float4 a01 = __ldg(&atom_ft[(long long)s.y * DV + lane]);

    float4 bf1, a10, a11;
    if (has_b1) {
        bf1 = __ldcs(&bond_ft[(long long)b1 * DV + lane]);
        a10 = __ldg(&atom_ft[(long long)s.z * DV + lane]);
        a11 = __ldg(&atom_ft[(long long)s.w * DV + lane]);
    }

    // ---- bond 0 ----
    {
        float4 mean_v, max_v;
        mean_v.x = (a00.x + a01.x) * 0.5f;  max_v.x = fmaxf(a00.x, a01.x);
        mean_v.y = (a00.y + a01.y) * 0.5f;  max_v.y = fmaxf(a00.y, a01.y);
        mean_v.z = (a00.z + a01.z) * 0.5f;  max_v.z = fmaxf(a00.z, a01.z);
        mean_v.w = (a00.w + a01.w) * 0.5f;  max_v.w = fmaxf(a00.w, a01.w);

        float4* orow = out + (long long)b0 * (3 * DV);
        __stcs(orow + lane,          bf0);
        __stcs(orow + DV + lane,     mean_v);
        __stcs(orow + 2 * DV + lane, max_v);
    }

    // ---- bond 1 ----
    if (has_b1) {
        float4 mean_v, max_v;
        mean_v.x = (a10.x + a11.x) * 0.5f;  max_v.x = fmaxf(a10.x, a11.x);
        mean_v.y = (a10.y + a11.y) * 0.5f;  max_v.y = fmaxf(a10.y, a11.y);
        mean_v.z = (a10.z + a11.z) * 0.5f;  max_v.z = fmaxf(a10.z, a11.z);
        mean_v.w = (a10.w + a11.w) * 0.5f;  max_v.w = fmaxf(a10.w, a11.w);

        float4* orow = out + (long long)b1 * (3 * DV);
        __stcs(orow + lane,          bf1);
        __stcs(orow + DV + lane,     mean_v);
        __stcs(orow + 2 * DV + lane, max_v);
    }
}

extern "C" void kernel_launch(void* const* d_in, const int* in_sizes, int n_in,
                              void* d_out, int out_size)
{
    const float4* atom_ft  = (const float4*)d_in[0];   // [N_ATOMS, 128] f32
    const float4* bond_ft  = (const float4*)d_in[1];   // [N_BONDS, 128] f32
    const int4*   edge_src = (const int4*)d_in[2];     // [N_BONDS*2] i32 -> int4 per 2 bonds
    // d_in[3] = edge_dst (structurally repeat(arange, 2)) -- not needed.

    const int n_bonds = in_sizes[1] / D;

    const int threads = 256;                         // 8 warps = 16 bonds/block
    const int bonds_per_block = (threads / 32) * 2;
    const int blocks = (n_bonds + bonds_per_block - 1) / bonds_per_block;

    concat_mean_max_kernel<<<blocks, threads>>>(
        atom_ft, bond_ft, edge_src, (float4*)d_out, n_bonds);
}